// round 13
// baseline (speedup 1.0000x reference)
#include <cuda_runtime.h>
#include <math.h>

// ---------------------------------------------------------------------------
// HMM forward (CgpHmmCell, nCodons=2): 24 states, CTX=6.
// Lane = state.  TWO rows per warp: row A exchanges via 4 width-32 shfls,
// row B via 1 STS + 4 LDS (in-order per-warp MIO), so the two serial chains
// use different pipes and overlap.  2-step composite rounds (tables T1=110KB
// + Bt=27KB, both L1-resident).  (T,E) prefetched one round ahead into regs.
// Deferred exact power-of-two renorm every 16 steps.
// ---------------------------------------------------------------------------

__device__ float  g_A[24 * 24];      // dense softmaxed transition matrix
__device__ float  g_Bt[216 * 32];    // emission: Bt[ctx*32 + state] (pad 0)
__device__ float  g_pi[32];          // softmax(init), lanes>=24 -> 0
__device__ float4 g_W1[32];          // single-step weights A[src_k][s]
__device__ float4 g_T1[216 * 32];    // 2-step composite weights per (ctx1, s)

// row softmax structure of A
__constant__ int c_rcnt[24] = {2,1,1,4,1,1,3,1,1,2,1,1,1,2,1,1,2,1,1,2,1,1,2,1};
__constant__ int c_rcols[24][4] = {
  {0,1,0,0},{2,0,0,0},{3,0,0,0},{4,14,7,10},{5,0,0,0},{6,0,0,0},{7,17,10,0},
  {8,0,0,0},{9,0,0,0},{20,10,0,0},{11,0,0,0},{12,0,0,0},{13,0,0,0},{13,23,0,0},
  {15,0,0,0},{16,0,0,0},{4,14,0,0},{18,0,0,0},{19,0,0,0},{7,17,0,0},{21,0,0,0},
  {22,0,0,0},{10,20,0,0},{23,0,0,0}};

// 1-step in-lists
__constant__ int c_cnt1[32] = {1,1,1,1,2,1,1,3,1,1,4,1,1,2,2,1,1,2,1,1,2,1,1,2,
                               0,0,0,0,0,0,0,0};
__constant__ int c_in1[32][4] = {
  {0,0,0,0},{0,0,0,0},{1,0,0,0},{2,0,0,0},{3,16,0,0},{4,0,0,0},{5,0,0,0},
  {3,6,19,0},{7,0,0,0},{8,0,0,0},{3,6,9,22},{10,0,0,0},{11,0,0,0},{12,13,0,0},
  {3,16,0,0},{14,0,0,0},{15,0,0,0},{6,19,0,0},{17,0,0,0},{18,0,0,0},{9,22,0,0},
  {20,0,0,0},{21,0,0,0},{13,23,0,0},
  {0,0,0,0},{0,0,0,0},{0,0,0,0},{0,0,0,0},{0,0,0,0},{0,0,0,0},{0,0,0,0},{0,0,0,0}};

// 2-step in-lists
__constant__ int c_cnt2[32] = {1,1,1,1,2,2,1,3,3,1,4,4,1,3,2,2,1,2,2,1,2,2,1,3,
                               0,0,0,0,0,0,0,0};
__constant__ int c_in2[32][4] = {
  {0,0,0,0},{0,0,0,0},{0,0,0,0},{1,0,0,0},{2,15,0,0},{3,16,0,0},{4,0,0,0},
  {2,5,18,0},{3,6,19,0},{7,0,0,0},{2,5,8,21},{3,6,9,22},{10,0,0,0},
  {11,12,13,0},{2,15,0,0},{3,16,0,0},{14,0,0,0},{5,18,0,0},{6,19,0,0},
  {17,0,0,0},{8,21,0,0},{9,22,0,0},{20,0,0,0},{12,13,23,0},
  {0,0,0,0},{0,0,0,0},{0,0,0,0},{0,0,0,0},{0,0,0,0},{0,0,0,0},{0,0,0,0},{0,0,0,0}};

// ---------------------------------------------------------------------------
// setupA: A (sparse row softmax), W1, pi, publish g_A.  Small single block.
// ---------------------------------------------------------------------------
__global__ void setupA_kernel(const float* __restrict__ w,
                              const float* __restrict__ ik) {
  __shared__ float V[24][24];
  __shared__ float A[24][24];
  int tid = threadIdx.x;
  for (int i = tid; i < 576; i += blockDim.x) {
    ((float*)V)[i] = 0.f;
    ((float*)A)[i] = 0.f;
  }
  __syncthreads();
  if (tid == 0) {
    float w12 = w[12];
    V[0][0]  = 1.f - w[0]; V[0][1]  = w[0];
    V[1][2]  = 1.f;        V[2][3]  = 1.f;
    V[3][4]  = w[1];       V[6][7]  = w[2];
    V[4][5]  = 1.f; V[7][8] = 1.f; V[5][6] = 1.f; V[8][9] = 1.f;
    V[3][14] = w[3]; V[6][17] = w[4]; V[9][20] = w[5];
    V[9][10] = 1.f - w[5];
    V[14][15] = 1.f; V[17][18] = 1.f; V[20][21] = 1.f;
    V[15][16] = 1.f; V[18][19] = 1.f; V[21][22] = 1.f;
    V[16][4] = w[6]; V[19][7] = w[7]; V[22][10] = w[8];
    V[16][14] = 1.f - w[9]; V[19][17] = 1.f - w[10]; V[22][20] = 1.f - w[11];
    V[3][7]  = 1.f - w12 * w12;
    V[3][10] = 1.f - w12 * w12 * w12;
    V[6][10] = 1.f - w12 * w12;
    V[10][11] = 1.f; V[11][12] = 1.f; V[12][13] = 1.f;
    V[13][13] = 1.f; V[13][23] = 1.f; V[23][23] = 1.f;
  }
  __syncthreads();
  if (tid < 24) {
    int n = c_rcnt[tid];
    float m = -1e30f;
    for (int i = 0; i < n; ++i) m = fmaxf(m, V[tid][c_rcols[tid][i]]);
    float Z = 0.f;
    for (int i = 0; i < n; ++i) Z += __expf(V[tid][c_rcols[tid][i]] - m);
    for (int i = 0; i < n; ++i) {
      int c = c_rcols[tid][i];
      A[tid][c] = __expf(V[tid][c] - m) / Z;
    }
  }
  __syncthreads();
  for (int i = tid; i < 576; i += blockDim.x) g_A[i] = ((float*)A)[i];
  if (tid < 32) {
    float4 wv = make_float4(0.f, 0.f, 0.f, 0.f);
    int n = c_cnt1[tid];
    if (n > 0) wv.x = A[c_in1[tid][0]][tid];
    if (n > 1) wv.y = A[c_in1[tid][1]][tid];
    if (n > 2) wv.z = A[c_in1[tid][2]][tid];
    if (n > 3) wv.w = A[c_in1[tid][3]][tid];
    g_W1[tid] = wv;
  }
  if (tid == 32) {
    float m = -1e30f;
    for (int s = 0; s < 24; ++s) m = fmaxf(m, ik[s]);
    float Z = 0.f;
    for (int s = 0; s < 24; ++s) Z += __expf(ik[s] - m);
    for (int s = 0; s < 32; ++s)
      g_pi[s] = (s < 24) ? __expf(ik[s] - m) / Z : 0.f;
  }
}

// ---------------------------------------------------------------------------
// setupB: emission table Bt (parallel across 27 blocks)
// ---------------------------------------------------------------------------
__global__ void setupB_kernel(const float* __restrict__ ew) {
  int idx = blockIdx.x * 256 + threadIdx.x;   // 27*256 = 6912 = 216*32
  int s = idx & 31, ctx = idx >> 5;
  int pp = ctx / 36, rm = ctx - pp * 36;
  int p = rm / 6, c = rm - p * 6;
  float val = 0.f;
  if (s < 24) {
    val = 1.f / 6.f;
    if (s < 17 && pp < 4 && p < 4 && c < 4) {
      const float* e = ew + (((s * 4) + pp) * 4 + p) * 4;
      float m = fmaxf(fmaxf(e[0], e[1]), fmaxf(e[2], e[3]));
      float Z = __expf(e[0] - m) + __expf(e[1] - m) +
                __expf(e[2] - m) + __expf(e[3] - m);
      val = __expf(e[c] - m) / Z;
    }
  }
  g_Bt[idx] = val;
}

// ---------------------------------------------------------------------------
// setupT: T1[ctx][s].k = sum over 2-paths (q=in2_k -> m -> s) of
//         A[q][m] * E_ctx[m] * A[m][s]
// ---------------------------------------------------------------------------
__global__ void setupT_kernel() {
  int ctx = blockIdx.x;      // 216 blocks
  int s = threadIdx.x;       // 32 threads
  float co[4] = {0.f, 0.f, 0.f, 0.f};
  if (s < 24) {
    int n1 = c_cnt1[s];
    for (int a = 0; a < n1; ++a) {
      int m = c_in1[s][a];
      float wms = g_A[m * 24 + s] * g_Bt[ctx * 32 + m];
      int nm = c_cnt1[m];
      for (int b = 0; b < nm; ++b) {
        int q = c_in1[m][b];
        float wqm = g_A[q * 24 + m];
        int n2 = c_cnt2[s];
        for (int k = 0; k < n2; ++k)
          if (c_in2[s][k] == q) { co[k] += wqm * wms; break; }
      }
    }
  }
  g_T1[ctx * 32 + s] = make_float4(co[0], co[1], co[2], co[3]);
}

// ---------------------------------------------------------------------------
// pack 16 ctx indices (8 bits each) into 4 uints; explicit (pr, m1) carry
#define PACKW(dst, pr, m1, sx, sy, sz, sw)                             \
  {                                                                    \
    int _c0 = pr * 6 + (sx); pr = m1 * 6 + (sx); m1 = (sx);            \
    int _c1 = pr * 6 + (sy); pr = m1 * 6 + (sy); m1 = (sy);            \
    int _c2 = pr * 6 + (sz); pr = m1 * 6 + (sz); m1 = (sz);            \
    int _c3 = pr * 6 + (sw); pr = m1 * 6 + (sw); m1 = (sw);            \
    dst = (unsigned)_c0 | ((unsigned)_c1 << 8) | ((unsigned)_c2 << 16) \
        | ((unsigned)_c3 << 24);                                       \
  }

// dual 2-step round.  Computes one round for row A (shfl pipe) and row B
// (STS/LDS pipe) using the CURRENT (T,E) buffers, while prefetching the NEXT
// round's (T,E) for both rows from packed descriptors.
#define DRND(pkA, shA, pkB, shB)                                            \
  {                                                                         \
    unsigned _wA = (pkA) >> (shA);                                          \
    float4 _TnA = T1p[(int)(_wA & 255u) * 32 + lane];                       \
    float  _EnA = Btp[(int)((_wA >> 8) & 255u) * 32 + lane];                \
    unsigned _wB = (pkB) >> (shB);                                          \
    float4 _TnB = T1p[(int)(_wB & 255u) * 32 + lane];                       \
    float  _EnB = Btp[(int)((_wB >> 8) & 255u) * 32 + lane];                \
    asm volatile("st.shared.f32 [%0], %1;" :: "r"(sb), "f"(aB));            \
    float _q0 = __shfl_sync(F, aA, sA0);                                    \
    float _q1 = __shfl_sync(F, aA, sA1);                                    \
    float _q2 = __shfl_sync(F, aA, sA2);                                    \
    float _q3 = __shfl_sync(F, aA, sA3);                                    \
    float _r0, _r1, _r2, _r3;                                               \
    asm volatile("ld.shared.f32 %0, [%1];" : "=f"(_r0) : "r"(rb0));         \
    asm volatile("ld.shared.f32 %0, [%1];" : "=f"(_r1) : "r"(rb1));         \
    asm volatile("ld.shared.f32 %0, [%1];" : "=f"(_r2) : "r"(rb2));         \
    asm volatile("ld.shared.f32 %0, [%1];" : "=f"(_r3) : "r"(rb3));         \
    aA = (fmaf(TA.y, _q1, TA.x * _q0) + fmaf(TA.w, _q3, TA.z * _q2)) * EA;  \
    aB = (fmaf(TB.y, _r1, TB.x * _r0) + fmaf(TB.w, _r3, TB.z * _r2)) * EB;  \
    TA = _TnA; EA = _EnA; TB = _TnB; EB = _EnB;                             \
  }

// lagged exact power-of-two renorm for one alpha (full-warp butterfly)
#define RENORM(AV, PEND, EK, KK, ZL)                            \
  {                                                             \
    AV *= PEND;                                                 \
    KK += (float)EK;                                            \
    float _z = AV;                                              \
    _z += __shfl_xor_sync(F, _z, 16);                           \
    _z += __shfl_xor_sync(F, _z, 8);                            \
    _z += __shfl_xor_sync(F, _z, 4);                            \
    _z += __shfl_xor_sync(F, _z, 2);                            \
    _z += __shfl_xor_sync(F, _z, 1);                            \
    int _ez = ((__float_as_int(_z) >> 23) & 0xff) - 127;        \
    PEND = __int_as_float((127 - _ez) << 23);                   \
    EK = _ez;                                                   \
    ZL = _z;                                                    \
  }

__global__ void __launch_bounds__(128)
fwd_kernel(const int* __restrict__ seq, float* __restrict__ out, int T) {
  const unsigned F = 0xffffffffu;
  __shared__ float xch[4][32];
  int lane = threadIdx.x & 31;
  int wid = threadIdx.x >> 5;
  int rA = blockIdx.x * 8 + wid * 2;
  int rB = rA + 1;
  const int4* spA = (const int4*)(seq + (long long)rA * T);
  const int4* spB = (const int4*)(seq + (long long)rB * T);

  const float4* T1p = g_T1;
  const float*  Btp = g_Bt;

  // smem exchange addresses (row B)
  unsigned sbase;
  asm("{ .reg .u64 t; cvta.to.shared.u64 t, %1; cvt.u32.u64 %0, t; }"
      : "=r"(sbase) : "l"(&xch[wid][0]));
  unsigned sb  = sbase + (unsigned)(lane * 4);
  unsigned rb0 = sbase + (unsigned)(c_in2[lane][0] * 4);
  unsigned rb1 = sbase + (unsigned)(c_in2[lane][1] * 4);
  unsigned rb2 = sbase + (unsigned)(c_in2[lane][2] * 4);
  unsigned rb3 = sbase + (unsigned)(c_in2[lane][3] * 4);
  // shfl source lanes (row A)
  int sA0 = c_in2[lane][0], sA1 = c_in2[lane][1];
  int sA2 = c_in2[lane][2], sA3 = c_in2[lane][3];

  float4 W1 = g_W1[lane];
  int s10 = c_in1[lane][0], s11 = c_in1[lane][1];
  int s12 = c_in1[lane][2], s13 = c_in1[lane][3];

  float aA = g_pi[lane], aB = aA;

  int prA = 28, m1A = 4, prB = 28, m1B = 4;   // start-context (4,4)
  float KA = 0.f, pendA = 1.f, zlA = 1.f;  int eKA = 0;
  float KB = 0.f, pendB = 1.f, zlB = 1.f;  int eKB = 0;

  // --- block 0 packed ctx ---------------------------------------------------
  unsigned cwA0, cwA1, cwA2, cwA3, cwB0, cwB1, cwB2, cwB3;
  {
    int4 t0 = spA[0], t1 = spA[1], t2 = spA[2], t3 = spA[3];
    PACKW(cwA0, prA, m1A, t0.x, t0.y, t0.z, t0.w);
    PACKW(cwA1, prA, m1A, t1.x, t1.y, t1.z, t1.w);
    PACKW(cwA2, prA, m1A, t2.x, t2.y, t2.z, t2.w);
    PACKW(cwA3, prA, m1A, t3.x, t3.y, t3.z, t3.w);
    int4 u0 = spB[0], u1 = spB[1], u2 = spB[2], u3 = spB[3];
    PACKW(cwB0, prB, m1B, u0.x, u0.y, u0.z, u0.w);
    PACKW(cwB1, prB, m1B, u1.x, u1.y, u1.z, u1.w);
    PACKW(cwB2, prB, m1B, u2.x, u2.y, u2.z, u2.w);
    PACKW(cwB3, prB, m1B, u3.x, u3.y, u3.z, u3.w);
  }

  // --- t = 0 and t = 1 (both rows, shfl single-step) ------------------------
  {
    aA *= Btp[(int)(cwA0 & 255u) * 32 + lane];
    aB *= Btp[(int)(cwB0 & 255u) * 32 + lane];
    float eA = Btp[(int)((cwA0 >> 8) & 255u) * 32 + lane];
    float eB = Btp[(int)((cwB0 >> 8) & 255u) * 32 + lane];
    float p0 = __shfl_sync(F, aA, s10);
    float p1 = __shfl_sync(F, aA, s11);
    float p2 = __shfl_sync(F, aA, s12);
    float p3 = __shfl_sync(F, aA, s13);
    aA = (fmaf(W1.y, p1, W1.x * p0) + fmaf(W1.w, p3, W1.z * p2)) * eA;
    float q0 = __shfl_sync(F, aB, s10);
    float q1 = __shfl_sync(F, aB, s11);
    float q2 = __shfl_sync(F, aB, s12);
    float q3 = __shfl_sync(F, aB, s13);
    aB = (fmaf(W1.y, q1, W1.x * q0) + fmaf(W1.w, q3, W1.z * q2)) * eB;
  }

  // --- preload round (cw0,16) into current buffers --------------------------
  float4 TA, TB; float EA, EB;
  {
    unsigned wA = cwA0 >> 16;
    TA = T1p[(int)(wA & 255u) * 32 + lane];
    EA = Btp[(int)((wA >> 8) & 255u) * 32 + lane];
    unsigned wB = cwB0 >> 16;
    TB = T1p[(int)(wB & 255u) * 32 + lane];
    EB = Btp[(int)((wB >> 8) & 255u) * 32 + lane];
  }

  unsigned nwA0, nwA1, nwA2, nwA3, nwB0, nwB1, nwB2, nwB3;
  // --- block 0: 7 rounds (steps 2..15) --------------------------------------
  {
    int4 t0 = spA[4], t1 = spA[5], t2 = spA[6], t3 = spA[7];
    PACKW(nwA0, prA, m1A, t0.x, t0.y, t0.z, t0.w);
    PACKW(nwA1, prA, m1A, t1.x, t1.y, t1.z, t1.w);
    PACKW(nwA2, prA, m1A, t2.x, t2.y, t2.z, t2.w);
    PACKW(nwA3, prA, m1A, t3.x, t3.y, t3.z, t3.w);
    int4 u0 = spB[4], u1 = spB[5], u2 = spB[6], u3 = spB[7];
    PACKW(nwB0, prB, m1B, u0.x, u0.y, u0.z, u0.w);
    PACKW(nwB1, prB, m1B, u1.x, u1.y, u1.z, u1.w);
    PACKW(nwB2, prB, m1B, u2.x, u2.y, u2.z, u2.w);
    PACKW(nwB3, prB, m1B, u3.x, u3.y, u3.z, u3.w);

    DRND(cwA1, 0, cwB1, 0);   DRND(cwA1, 16, cwB1, 16);
    DRND(cwA2, 0, cwB2, 0);   DRND(cwA2, 16, cwB2, 16);
    DRND(cwA3, 0, cwB3, 0);   DRND(cwA3, 16, cwB3, 16);
    DRND(nwA0, 0, nwB0, 0);
    RENORM(aA, pendA, eKA, KA, zlA);
    RENORM(aB, pendB, eKB, KB, zlB);

    cwA0 = nwA0; cwA1 = nwA1; cwA2 = nwA2; cwA3 = nwA3;
    cwB0 = nwB0; cwB1 = nwB1; cwB2 = nwB2; cwB3 = nwB3;
  }

  // --- main: 124 blocks x 8 rounds (steps 16..1999) -------------------------
  for (int i = 1; i < 125; ++i) {
    {
      int nb = (i + 1 < 125) ? (i + 1) : 0;   // last iter: dummy, unused
      int4 t0 = spA[nb*4+0], t1 = spA[nb*4+1], t2 = spA[nb*4+2], t3 = spA[nb*4+3];
      PACKW(nwA0, prA, m1A, t0.x, t0.y, t0.z, t0.w);
      PACKW(nwA1, prA, m1A, t1.x, t1.y, t1.z, t1.w);
      PACKW(nwA2, prA, m1A, t2.x, t2.y, t2.z, t2.w);
      PACKW(nwA3, prA, m1A, t3.x, t3.y, t3.z, t3.w);
      int4 u0 = spB[nb*4+0], u1 = spB[nb*4+1], u2 = spB[nb*4+2], u3 = spB[nb*4+3];
      PACKW(nwB0, prB, m1B, u0.x, u0.y, u0.z, u0.w);
      PACKW(nwB1, prB, m1B, u1.x, u1.y, u1.z, u1.w);
      PACKW(nwB2, prB, m1B, u2.x, u2.y, u2.z, u2.w);
      PACKW(nwB3, prB, m1B, u3.x, u3.y, u3.z, u3.w);
    }

    DRND(cwA0, 16, cwB0, 16);
    DRND(cwA1, 0, cwB1, 0);   DRND(cwA1, 16, cwB1, 16);
    DRND(cwA2, 0, cwB2, 0);   DRND(cwA2, 16, cwB2, 16);
    DRND(cwA3, 0, cwB3, 0);   DRND(cwA3, 16, cwB3, 16);
    DRND(nwA0, 0, nwB0, 0);
    RENORM(aA, pendA, eKA, KA, zlA);
    RENORM(aB, pendB, eKB, KB, zlB);

    cwA0 = nwA0; cwA1 = nwA1; cwA2 = nwA2; cwA3 = nwA3;
    cwB0 = nwB0; cwB1 = nwB1; cwB2 = nwB2; cwB3 = nwB3;
  }

  if (lane == 0) {
    out[rA] = (__log2f(zlA) + KA) * 0.69314718055994530942f;
    out[rB] = (__log2f(zlB) + KB) * 0.69314718055994530942f;
  }
}

// ---------------------------------------------------------------------------
extern "C" void kernel_launch(void* const* d_in, const int* in_sizes, int n_in,
                              void* d_out, int out_size) {
  const float* w  = (const float*)d_in[0];   // transition_kernel (240)
  const float* ew = (const float*)d_in[1];   // emission_kernel (1088)
  const float* ik = (const float*)d_in[2];   // init_kernel (24)
  const int* seq  = (const int*)d_in[3];     // (batch, T)
  float* out = (float*)d_out;

  int batch = out_size;                      // 2048
  int T = in_sizes[3] / batch;               // 2000

  setupA_kernel<<<1, 64>>>(w, ik);
  setupB_kernel<<<27, 256>>>(ew);
  setupT_kernel<<<216, 32>>>();
  fwd_kernel<<<batch / 8, 128>>>(seq, out, T);
}

// round 14
// speedup vs baseline: 1.5094x; 1.5094x over previous
#include <cuda_runtime.h>
#include <math.h>

// ---------------------------------------------------------------------------
// HMM forward (CgpHmmCell, nCodons=2), 24 states, CTX=6, T=2000, batch=2048.
// TRANSPOSED layout: one LANE holds the full 24-state vector in registers;
// lane = (row, half).  No cross-lane exchange at all: the sparse matvec is 35
// in-register FMAs (+24 emission muls), weights in registers, emissions from
// a 20.7KB smem table (6x LDS.128/step, consumed at step end -> latency
// hidden under the matvec).  Time split 2-way exactly:
//   fwd half:  alpha_t = E_t * (A^T alpha_{t-1}),  t = 0..999
//   bwd half:  m_t     = E_t * (A    m_{t+1}),     t = 1999..1000,  m_1999=E
//   loglik = log( (A m_1000) . alpha_999 ) + (K_f + K_b) ln 2
// 4096 lane-tasks = 128 warps = 128 CTAs x 32 threads (one warp per SMSP,
// spread over 128 SMs).  Per-lane scalar power-of-2 renorm (exact).
// ---------------------------------------------------------------------------

__device__ float g_Av[576];          // dense softmaxed A
__device__ float g_Wv[35];           // the 35 structural edge weights
__device__ float g_piv[24];          // softmax(init)
__device__ float g_BtV[216 * 24];    // emission B[ctx][state]
__device__ float g_vec[4096][24];    // half-results (fwd: alpha, bwd: u)
__device__ float g_Kv[4096];         // accumulated power-of-2 exponents

__constant__ int c_rcnt[24] = {2,1,1,4,1,1,3,1,1,2,1,1,1,2,1,1,2,1,1,2,1,1,2,1};
__constant__ int c_rcols[24][4] = {
  {0,1,0,0},{2,0,0,0},{3,0,0,0},{4,14,7,10},{5,0,0,0},{6,0,0,0},{7,17,10,0},
  {8,0,0,0},{9,0,0,0},{20,10,0,0},{11,0,0,0},{12,0,0,0},{13,0,0,0},{13,23,0,0},
  {15,0,0,0},{16,0,0,0},{4,14,0,0},{18,0,0,0},{19,0,0,0},{7,17,0,0},{21,0,0,0},
  {22,0,0,0},{10,20,0,0},{23,0,0,0}};

// ---------------------------------------------------------------------------
__global__ void setup_kernel(const float* __restrict__ w,
                             const float* __restrict__ ew,
                             const float* __restrict__ ik) {
  __shared__ float V[24][24];
  __shared__ float A[24][24];
  int tid = threadIdx.x;
  for (int i = tid; i < 576; i += blockDim.x) {
    ((float*)V)[i] = 0.f;
    ((float*)A)[i] = 0.f;
  }
  __syncthreads();
  if (tid == 0) {
    float w12 = w[12];
    V[0][0]  = 1.f - w[0]; V[0][1]  = w[0];
    V[1][2]  = 1.f;        V[2][3]  = 1.f;
    V[3][4]  = w[1];       V[6][7]  = w[2];
    V[4][5]  = 1.f; V[7][8] = 1.f; V[5][6] = 1.f; V[8][9] = 1.f;
    V[3][14] = w[3]; V[6][17] = w[4]; V[9][20] = w[5];
    V[9][10] = 1.f - w[5];
    V[14][15] = 1.f; V[17][18] = 1.f; V[20][21] = 1.f;
    V[15][16] = 1.f; V[18][19] = 1.f; V[21][22] = 1.f;
    V[16][4] = w[6]; V[19][7] = w[7]; V[22][10] = w[8];
    V[16][14] = 1.f - w[9]; V[19][17] = 1.f - w[10]; V[22][20] = 1.f - w[11];
    V[3][7]  = 1.f - w12 * w12;
    V[3][10] = 1.f - w12 * w12 * w12;
    V[6][10] = 1.f - w12 * w12;
    V[10][11] = 1.f; V[11][12] = 1.f; V[12][13] = 1.f;
    V[13][13] = 1.f; V[13][23] = 1.f; V[23][23] = 1.f;
  }
  __syncthreads();
  if (tid < 24) {
    int n = c_rcnt[tid];
    float m = -1e30f;
    for (int i = 0; i < n; ++i) m = fmaxf(m, V[tid][c_rcols[tid][i]]);
    float Z = 0.f;
    for (int i = 0; i < n; ++i) Z += __expf(V[tid][c_rcols[tid][i]] - m);
    for (int i = 0; i < n; ++i) {
      int c = c_rcols[tid][i];
      A[tid][c] = __expf(V[tid][c] - m) / Z;
    }
  }
  __syncthreads();
  for (int i = tid; i < 576; i += blockDim.x) g_Av[i] = ((float*)A)[i];
  if (tid == 0) {
    g_Wv[0]=A[0][0];   g_Wv[1]=A[0][1];   g_Wv[2]=A[1][2];   g_Wv[3]=A[2][3];
    g_Wv[4]=A[3][4];   g_Wv[5]=A[16][4];  g_Wv[6]=A[4][5];   g_Wv[7]=A[5][6];
    g_Wv[8]=A[3][7];   g_Wv[9]=A[6][7];   g_Wv[10]=A[19][7]; g_Wv[11]=A[7][8];
    g_Wv[12]=A[8][9];  g_Wv[13]=A[3][10]; g_Wv[14]=A[6][10]; g_Wv[15]=A[9][10];
    g_Wv[16]=A[22][10];g_Wv[17]=A[10][11];g_Wv[18]=A[11][12];g_Wv[19]=A[12][13];
    g_Wv[20]=A[13][13];g_Wv[21]=A[3][14]; g_Wv[22]=A[16][14];g_Wv[23]=A[14][15];
    g_Wv[24]=A[15][16];g_Wv[25]=A[6][17]; g_Wv[26]=A[19][17];g_Wv[27]=A[17][18];
    g_Wv[28]=A[18][19];g_Wv[29]=A[9][20]; g_Wv[30]=A[22][20];g_Wv[31]=A[20][21];
    g_Wv[32]=A[21][22];g_Wv[33]=A[13][23];g_Wv[34]=A[23][23];
  }
  if (tid == 33) {
    float m = -1e30f;
    for (int s = 0; s < 24; ++s) m = fmaxf(m, ik[s]);
    float Z = 0.f;
    for (int s = 0; s < 24; ++s) Z += __expf(ik[s] - m);
    for (int s = 0; s < 24; ++s) g_piv[s] = __expf(ik[s] - m) / Z;
  }
  // emission table B[ctx][s], ctx = pp*36 + p*6 + c
  for (int idx = tid; idx < 216 * 24; idx += blockDim.x) {
    int s = idx % 24, ctx = idx / 24;
    int pp = ctx / 36, rm = ctx - pp * 36;
    int p = rm / 6, c = rm - p * 6;
    float val = 1.f / 6.f;
    if (s < 17 && pp < 4 && p < 4 && c < 4) {
      const float* e = ew + (((s * 4) + pp) * 4 + p) * 4;
      float m = fmaxf(fmaxf(e[0], e[1]), fmaxf(e[2], e[3]));
      float Z = __expf(e[0] - m) + __expf(e[1] - m) +
                __expf(e[2] - m) + __expf(e[3] - m);
      val = __expf(e[c] - m) / Z;
    }
    g_BtV[idx] = val;
  }
}

// ---------------------------------------------------------------------------
// emission load: 6x LDS.128 from the per-CTA smem table
#define ELOAD(CTX)                                                          \
  const float* _ep = sBt + (CTX) * 24;                                      \
  float4 _e0 = *(const float4*)(_ep);      float4 _e1 = *(const float4*)(_ep + 4);  \
  float4 _e2 = *(const float4*)(_ep + 8);  float4 _e3 = *(const float4*)(_ep + 12); \
  float4 _e4 = *(const float4*)(_ep + 16); float4 _e5 = *(const float4*)(_ep + 20);

#define EAPPLY()                                                            \
  a0 = n0*_e0.x;  a1 = n1*_e0.y;  a2 = n2*_e0.z;  a3 = n3*_e0.w;            \
  a4 = n4*_e1.x;  a5 = n5*_e1.y;  a6 = n6*_e1.z;  a7 = n7*_e1.w;            \
  a8 = n8*_e2.x;  a9 = n9*_e2.y;  a10= n10*_e2.z; a11= n11*_e2.w;           \
  a12= n12*_e3.x; a13= n13*_e3.y; a14= n14*_e3.z; a15= n15*_e3.w;           \
  a16= n16*_e4.x; a17= n17*_e4.y; a18= n18*_e4.z; a19= n19*_e4.w;           \
  a20= n20*_e5.x; a21= n21*_e5.y; a22= n22*_e5.z; a23= n23*_e5.w;

// forward step: n = A^T a (35 ops), then a = n * E
#define FSTEP(CTX) {                                                        \
  ELOAD(CTX)                                                                \
  float n0 = W0*a0;                                                         \
  float n1 = W1*a0;                                                         \
  float n2 = W2*a1;                                                         \
  float n3 = W3*a2;                                                         \
  float n4 = fmaf(W5,a16, W4*a3);                                           \
  float n5 = W6*a4;                                                         \
  float n6 = W7*a5;                                                         \
  float n7 = fmaf(W10,a19, fmaf(W9,a6, W8*a3));                             \
  float n8 = W11*a7;                                                        \
  float n9 = W12*a8;                                                        \
  float n10 = fmaf(W16,a22, fmaf(W15,a9, fmaf(W14,a6, W13*a3)));            \
  float n11 = W17*a10;                                                      \
  float n12 = W18*a11;                                                      \
  float n13 = fmaf(W20,a13, W19*a12);                                       \
  float n14 = fmaf(W22,a16, W21*a3);                                        \
  float n15 = W23*a14;                                                      \
  float n16 = W24*a15;                                                      \
  float n17 = fmaf(W26,a19, W25*a6);                                        \
  float n18 = W27*a17;                                                      \
  float n19 = W28*a18;                                                      \
  float n20 = fmaf(W30,a22, W29*a9);                                        \
  float n21 = W31*a20;                                                      \
  float n22 = W32*a21;                                                      \
  float n23 = fmaf(W34,a23, W33*a13);                                       \
  EAPPLY() }

// backward step: n = A a (transposed matvec, 35 ops), then a = n * E
#define BSTEP(CTX) {                                                        \
  ELOAD(CTX)                                                                \
  float n0 = fmaf(W1,a1, W0*a0);                                            \
  float n1 = W2*a2;                                                         \
  float n2 = W3*a3;                                                         \
  float n3 = fmaf(W21,a14, fmaf(W13,a10, fmaf(W8,a7, W4*a4)));              \
  float n4 = W6*a5;                                                         \
  float n5 = W7*a6;                                                         \
  float n6 = fmaf(W25,a17, fmaf(W14,a10, W9*a7));                           \
  float n7 = W11*a8;                                                        \
  float n8 = W12*a9;                                                        \
  float n9 = fmaf(W29,a20, W15*a10);                                        \
  float n10 = W17*a11;                                                      \
  float n11 = W18*a12;                                                      \
  float n12 = W19*a13;                                                      \
  float n13 = fmaf(W33,a23, W20*a13);                                       \
  float n14 = W23*a15;                                                      \
  float n15 = W24*a16;                                                      \
  float n16 = fmaf(W22,a14, W5*a4);                                         \
  float n17 = W27*a18;                                                      \
  float n18 = W28*a19;                                                      \
  float n19 = fmaf(W26,a17, W10*a7);                                        \
  float n20 = W31*a21;                                                      \
  float n21 = W32*a22;                                                      \
  float n22 = fmaf(W30,a20, W16*a10);                                       \
  float n23 = W34*a23;                                                      \
  EAPPLY() }

// exact power-of-two renorm (per-lane scalar)
#define RENORM() {                                                          \
  float _z = (((a0+a1)+(a2+a3))+((a4+a5)+(a6+a7)))                          \
           + (((a8+a9)+(a10+a11))+((a12+a13)+(a14+a15)))                    \
           + (((a16+a17)+(a18+a19))+((a20+a21)+(a22+a23)));                 \
  int _ez = ((__float_as_int(_z) >> 23) & 0xff) - 127;                      \
  float _sc = __int_as_float((127 - _ez) << 23);                            \
  K += _ez;                                                                 \
  a0*=_sc; a1*=_sc; a2*=_sc; a3*=_sc; a4*=_sc; a5*=_sc;                     \
  a6*=_sc; a7*=_sc; a8*=_sc; a9*=_sc; a10*=_sc; a11*=_sc;                   \
  a12*=_sc; a13*=_sc; a14*=_sc; a15*=_sc; a16*=_sc; a17*=_sc;               \
  a18*=_sc; a19*=_sc; a20*=_sc; a21*=_sc; a22*=_sc; a23*=_sc; }

// fwd group g (4 steps), chunks prv = g-1, cur = g; prefetches g+1
#define GROUPF(g) {                                                         \
  int4 _nxt = sp[(g) + 1];                                                  \
  FSTEP(prv.z*36 + prv.w*6 + cur.x);                                        \
  FSTEP(prv.w*36 + cur.x*6 + cur.y);                                        \
  FSTEP(cur.x*36 + cur.y*6 + cur.z);                                        \
  FSTEP(cur.y*36 + cur.z*6 + cur.w);                                        \
  prv = cur; cur = _nxt; }

// bwd group g (4 steps, descending t = 4g+3..4g); chunks cur = g, prv = g-1
#define GROUPB(g) {                                                         \
  int4 _prv = sp[(g) - 1];                                                  \
  BSTEP(cur.y*36 + cur.z*6 + cur.w);                                        \
  BSTEP(cur.x*36 + cur.y*6 + cur.z);                                        \
  BSTEP(_prv.w*36 + cur.x*6 + cur.y);                                       \
  BSTEP(_prv.z*36 + _prv.w*6 + cur.x);                                      \
  cur = _prv; }

__global__ void __launch_bounds__(32)
scan_kernel(const int* __restrict__ seq, int T) {
  __shared__ __align__(16) float sBt[216 * 24];
  int lane = threadIdx.x;
  // copy emission table to smem (1296 float4)
  {
    const float4* srcp = (const float4*)g_BtV;
    float4* dstp = (float4*)sBt;
    for (int i = lane; i < 1296; i += 32) dstp[i] = srcp[i];
  }
  __syncwarp();

  int task = blockIdx.x * 32 + lane;
  int nb2 = (int)gridDim.x * 16;          // tasks per half = 2048
  int isF = task < nb2;
  int row = isF ? task : task - nb2;
  const int4* sp = (const int4*)(seq + (long long)row * T);

  float W0=g_Wv[0], W1=g_Wv[1], W2=g_Wv[2], W3=g_Wv[3], W4=g_Wv[4];
  float W5=g_Wv[5], W6=g_Wv[6], W7=g_Wv[7], W8=g_Wv[8], W9=g_Wv[9];
  float W10=g_Wv[10], W11=g_Wv[11], W12=g_Wv[12], W13=g_Wv[13], W14=g_Wv[14];
  float W15=g_Wv[15], W16=g_Wv[16], W17=g_Wv[17], W18=g_Wv[18], W19=g_Wv[19];
  float W20=g_Wv[20], W21=g_Wv[21], W22=g_Wv[22], W23=g_Wv[23], W24=g_Wv[24];
  float W25=g_Wv[25], W26=g_Wv[26], W27=g_Wv[27], W28=g_Wv[28], W29=g_Wv[29];
  float W30=g_Wv[30], W31=g_Wv[31], W32=g_Wv[32], W33=g_Wv[33], W34=g_Wv[34];

  float a0,a1,a2,a3,a4,a5,a6,a7,a8,a9,a10,a11,a12,a13,a14,a15,
        a16,a17,a18,a19,a20,a21,a22,a23;
  int K = 0;

  int HC = T / 8;            // 250 groups per half
  int n5 = (HC - 1) / 5;     // 49 full 5-group iterations
  int rem = (HC - 1) - n5 * 5;  // 4 remainder groups

  if (isF) {
    // ---- forward half: steps 0..T/2-1 --------------------------------------
    int4 cur = sp[0];
    {
      // t=0: a = pi * E(ctx 4,4,s0)
      const float* _p = g_piv;
      const float* _ep0 = sBt + (168 + cur.x) * 24;
      a0=_p[0]*_ep0[0];   a1=_p[1]*_ep0[1];   a2=_p[2]*_ep0[2];
      a3=_p[3]*_ep0[3];   a4=_p[4]*_ep0[4];   a5=_p[5]*_ep0[5];
      a6=_p[6]*_ep0[6];   a7=_p[7]*_ep0[7];   a8=_p[8]*_ep0[8];
      a9=_p[9]*_ep0[9];   a10=_p[10]*_ep0[10]; a11=_p[11]*_ep0[11];
      a12=_p[12]*_ep0[12]; a13=_p[13]*_ep0[13]; a14=_p[14]*_ep0[14];
      a15=_p[15]*_ep0[15]; a16=_p[16]*_ep0[16]; a17=_p[17]*_ep0[17];
      a18=_p[18]*_ep0[18]; a19=_p[19]*_ep0[19]; a20=_p[20]*_ep0[20];
      a21=_p[21]*_ep0[21]; a22=_p[22]*_ep0[22]; a23=_p[23]*_ep0[23];
      FSTEP(144 + cur.x*6 + cur.y);
      FSTEP(cur.x*36 + cur.y*6 + cur.z);
      FSTEP(cur.y*36 + cur.z*6 + cur.w);
    }
    int4 prv = cur;
    cur = sp[1];
    int g = 1;
    for (int it = 0; it < n5; ++it) {
      GROUPF(g); GROUPF(g + 1); GROUPF(g + 2); GROUPF(g + 3); GROUPF(g + 4);
      g += 5;
      RENORM();
    }
    for (int r = 0; r < rem; ++r) { GROUPF(g); ++g; }
  } else {
    // ---- backward half: m_t = E_t * (A m_{t+1}), t = T-1 .. T/2 ------------
    int CH = T / 4;                       // 500 chunks
    int4 cur = sp[CH - 1];
    int4 prv0 = sp[CH - 2];
    {
      // t = T-1: m = E(ctx)  (u_T = 1)
      const float* _ep0 = sBt + (cur.y*36 + cur.z*6 + cur.w) * 24;
      a0=_ep0[0];  a1=_ep0[1];  a2=_ep0[2];  a3=_ep0[3];
      a4=_ep0[4];  a5=_ep0[5];  a6=_ep0[6];  a7=_ep0[7];
      a8=_ep0[8];  a9=_ep0[9];  a10=_ep0[10]; a11=_ep0[11];
      a12=_ep0[12]; a13=_ep0[13]; a14=_ep0[14]; a15=_ep0[15];
      a16=_ep0[16]; a17=_ep0[17]; a18=_ep0[18]; a19=_ep0[19];
      a20=_ep0[20]; a21=_ep0[21]; a22=_ep0[22]; a23=_ep0[23];
      BSTEP(cur.x*36 + cur.y*6 + cur.z);
      BSTEP(prv0.w*36 + cur.x*6 + cur.y);
      BSTEP(prv0.z*36 + prv0.w*6 + cur.x);
    }
    cur = prv0;
    int g = CH - 2;                       // 498
    for (int it = 0; it < n5; ++it) {
      GROUPB(g); GROUPB(g - 1); GROUPB(g - 2); GROUPB(g - 3); GROUPB(g - 4);
      g -= 5;
      RENORM();
    }
    for (int r = 0; r < rem; ++r) { GROUPB(g); --g; }
    // final conversion: u = A m  (no emission)
    {
      float n0 = fmaf(W1,a1, W0*a0);
      float n1 = W2*a2;
      float n2 = W3*a3;
      float n3 = fmaf(W21,a14, fmaf(W13,a10, fmaf(W8,a7, W4*a4)));
      float n4 = W6*a5;
      float n5v = W7*a6;
      float n6 = fmaf(W25,a17, fmaf(W14,a10, W9*a7));
      float n7 = W11*a8;
      float n8 = W12*a9;
      float n9 = fmaf(W29,a20, W15*a10);
      float n10 = W17*a11;
      float n11 = W18*a12;
      float n12 = W19*a13;
      float n13 = fmaf(W33,a23, W20*a13);
      float n14 = W23*a15;
      float n15 = W24*a16;
      float n16 = fmaf(W22,a14, W5*a4);
      float n17 = W27*a18;
      float n18 = W28*a19;
      float n19 = fmaf(W26,a17, W10*a7);
      float n20 = W31*a21;
      float n21 = W32*a22;
      float n22 = fmaf(W30,a20, W16*a10);
      float n23 = W34*a23;
      a0=n0; a1=n1; a2=n2; a3=n3; a4=n4; a5=n5v; a6=n6; a7=n7;
      a8=n8; a9=n9; a10=n10; a11=n11; a12=n12; a13=n13; a14=n14; a15=n15;
      a16=n16; a17=n17; a18=n18; a19=n19; a20=n20; a21=n21; a22=n22; a23=n23;
    }
  }

  float* ov = g_vec[task];
  ov[0]=a0; ov[1]=a1; ov[2]=a2; ov[3]=a3; ov[4]=a4; ov[5]=a5;
  ov[6]=a6; ov[7]=a7; ov[8]=a8; ov[9]=a9; ov[10]=a10; ov[11]=a11;
  ov[12]=a12; ov[13]=a13; ov[14]=a14; ov[15]=a15; ov[16]=a16; ov[17]=a17;
  ov[18]=a18; ov[19]=a19; ov[20]=a20; ov[21]=a21; ov[22]=a22; ov[23]=a23;
  g_Kv[task] = (float)K;
}

// ---------------------------------------------------------------------------
__global__ void combine_kernel(float* __restrict__ out, int batch) {
  int r = blockIdx.x * 256 + threadIdx.x;
  if (r >= batch) return;
  const float* fa = g_vec[r];
  const float* fb = g_vec[r + batch];
  float dot = 0.f;
#pragma unroll
  for (int s = 0; s < 24; ++s) dot = fmaf(fa[s], fb[s], dot);
  out[r] = (__log2f(dot) + g_Kv[r] + g_Kv[r + batch]) *
           0.69314718055994530942f;
}

// ---------------------------------------------------------------------------
extern "C" void kernel_launch(void* const* d_in, const int* in_sizes, int n_in,
                              void* d_out, int out_size) {
  const float* w  = (const float*)d_in[0];   // transition_kernel (240)
  const float* ew = (const float*)d_in[1];   // emission_kernel (1088)
  const float* ik = (const float*)d_in[2];   // init_kernel (24)
  const int* seq  = (const int*)d_in[3];     // (batch, T)
  float* out = (float*)d_out;

  int batch = out_size;                      // 2048
  int T = in_sizes[3] / batch;               // 2000

  setup_kernel<<<1, 256>>>(w, ew, ik);
  scan_kernel<<<batch * 2 / 32, 32>>>(seq, T);
  combine_kernel<<<(batch + 255) / 256, 256>>>(out, batch);
}

// round 15
// speedup vs baseline: 1.6195x; 1.0730x over previous
#include <cuda_runtime.h>
#include <math.h>

// ---------------------------------------------------------------------------
// HMM forward (CgpHmmCell, nCodons=2), 24 states, T=2000, batch=2048.
// Transposed layout (R11): one lane owns the full 24-state vector; zero
// cross-lane exchange; fwd/bwd exact 2-way time split.
// R12: states packed into 12 f32x2 register pairs with pairing
//   (0,1)(2,3)(4,14)(5,15)(6,16)(7,17)(8,18)(9,19)(10,20)(11,21)(12,22)(13,23)
// chosen so the codon/insert chain symmetry makes most packed sources align.
// Matvec: 19 (fwd) / 21 (bwd) fma.rn.f32x2 ops + 12 packed E-muls per step
// (vs 59 scalar FMA-pipe ops).  E table stored in pair-permuted order so
// LDS.128 returns ready-packed pairs.  Exact power-of-2 renorm every 20 steps.
// ---------------------------------------------------------------------------

typedef unsigned long long u64;

__device__ u64 g_WFp[19];            // fwd packed weights
__device__ u64 g_WBp[21];            // bwd packed weights
__device__ u64 g_piP[12];            // packed softmax(init), pair order
__device__ __align__(16) float g_BtP[216 * 24];  // E[ctx][pair-permuted state]
__device__ u64 g_vecP[4096][12];     // half-results (packed)
__device__ float g_Kv[4096];         // accumulated exponents

__constant__ int c_rcnt[24] = {2,1,1,4,1,1,3,1,1,2,1,1,1,2,1,1,2,1,1,2,1,1,2,1};
__constant__ int c_rcols[24][4] = {
  {0,1,0,0},{2,0,0,0},{3,0,0,0},{4,14,7,10},{5,0,0,0},{6,0,0,0},{7,17,10,0},
  {8,0,0,0},{9,0,0,0},{20,10,0,0},{11,0,0,0},{12,0,0,0},{13,0,0,0},{13,23,0,0},
  {15,0,0,0},{16,0,0,0},{4,14,0,0},{18,0,0,0},{19,0,0,0},{7,17,0,0},{21,0,0,0},
  {22,0,0,0},{10,20,0,0},{23,0,0,0}};
// pair-permuted state order (column c of E table holds state c_perm[c])
__constant__ int c_perm[24] = {0,1, 2,3, 4,14, 5,15, 6,16, 7,17, 8,18, 9,19,
                               10,20, 11,21, 12,22, 13,23};

__device__ __forceinline__ u64 pk2(float lo, float hi) {
  return ((u64)__float_as_uint(hi) << 32) | (u64)__float_as_uint(lo);
}

// ---------------------------------------------------------------------------
// setupA: A (sparse row softmax), packed weights, packed pi.
// ---------------------------------------------------------------------------
__global__ void setupA_kernel(const float* __restrict__ w,
                              const float* __restrict__ ik) {
  __shared__ float V[24][24];
  __shared__ float A[24][24];
  int tid = threadIdx.x;
  for (int i = tid; i < 576; i += blockDim.x) {
    ((float*)V)[i] = 0.f;
    ((float*)A)[i] = 0.f;
  }
  __syncthreads();
  if (tid == 0) {
    float w12 = w[12];
    V[0][0]  = 1.f - w[0]; V[0][1]  = w[0];
    V[1][2]  = 1.f;        V[2][3]  = 1.f;
    V[3][4]  = w[1];       V[6][7]  = w[2];
    V[4][5]  = 1.f; V[7][8] = 1.f; V[5][6] = 1.f; V[8][9] = 1.f;
    V[3][14] = w[3]; V[6][17] = w[4]; V[9][20] = w[5];
    V[9][10] = 1.f - w[5];
    V[14][15] = 1.f; V[17][18] = 1.f; V[20][21] = 1.f;
    V[15][16] = 1.f; V[18][19] = 1.f; V[21][22] = 1.f;
    V[16][4] = w[6]; V[19][7] = w[7]; V[22][10] = w[8];
    V[16][14] = 1.f - w[9]; V[19][17] = 1.f - w[10]; V[22][20] = 1.f - w[11];
    V[3][7]  = 1.f - w12 * w12;
    V[3][10] = 1.f - w12 * w12 * w12;
    V[6][10] = 1.f - w12 * w12;
    V[10][11] = 1.f; V[11][12] = 1.f; V[12][13] = 1.f;
    V[13][13] = 1.f; V[13][23] = 1.f; V[23][23] = 1.f;
  }
  __syncthreads();
  if (tid < 24) {
    int n = c_rcnt[tid];
    float m = -1e30f;
    for (int i = 0; i < n; ++i) m = fmaxf(m, V[tid][c_rcols[tid][i]]);
    float Z = 0.f;
    for (int i = 0; i < n; ++i) Z += __expf(V[tid][c_rcols[tid][i]] - m);
    for (int i = 0; i < n; ++i) {
      int c = c_rcols[tid][i];
      A[tid][c] = __expf(V[tid][c] - m) / Z;
    }
  }
  __syncthreads();
  if (tid == 0) {
    float W0=A[0][0],  W1=A[0][1],  W2=A[1][2],  W3=A[2][3],  W4=A[3][4];
    float W5=A[16][4], W6=A[4][5],  W7=A[5][6],  W8=A[3][7],  W9=A[6][7];
    float W10=A[19][7],W11=A[7][8], W12=A[8][9], W13=A[3][10],W14=A[6][10];
    float W15=A[9][10],W16=A[22][10],W17=A[10][11],W18=A[11][12],W19=A[12][13];
    float W20=A[13][13],W21=A[3][14],W22=A[16][14],W23=A[14][15],W24=A[15][16];
    float W25=A[6][17],W26=A[19][17],W27=A[17][18],W28=A[18][19],W29=A[9][20];
    float W30=A[22][20],W31=A[20][21],W32=A[21][22],W33=A[13][23],W34=A[23][23];
    // fwd packed weights
    g_WFp[0]=pk2(W0,W1);   g_WFp[1]=pk2(W2,W3);   g_WFp[2]=pk2(W4,W21);
    g_WFp[3]=pk2(W5,W22);  g_WFp[4]=pk2(W6,W23);  g_WFp[5]=pk2(W7,W24);
    g_WFp[6]=pk2(W8,0.f);  g_WFp[7]=pk2(W9,W25);  g_WFp[8]=pk2(W10,W26);
    g_WFp[9]=pk2(W11,W27); g_WFp[10]=pk2(W12,W28);g_WFp[11]=pk2(W13,0.f);
    g_WFp[12]=pk2(W14,0.f);g_WFp[13]=pk2(W15,W29);g_WFp[14]=pk2(W16,W30);
    g_WFp[15]=pk2(W17,W31);g_WFp[16]=pk2(W18,W32);g_WFp[17]=pk2(W19,W33);
    g_WFp[18]=pk2(W20,W34);
    // bwd packed weights
    g_WBp[0]=pk2(W0,W2);   g_WBp[1]=pk2(W1,0.f);  g_WBp[2]=pk2(W3,W4);
    g_WBp[3]=pk2(0.f,W8);  g_WBp[4]=pk2(0.f,W13); g_WBp[5]=pk2(0.f,W21);
    g_WBp[6]=pk2(W6,W23);  g_WBp[7]=pk2(W7,W24);  g_WBp[8]=pk2(W9,W5);
    g_WBp[9]=pk2(W14,W22); g_WBp[10]=pk2(W25,0.f);g_WBp[11]=pk2(W11,W27);
    g_WBp[12]=pk2(W12,W28);g_WBp[13]=pk2(W15,W10);g_WBp[14]=pk2(W29,W26);
    g_WBp[15]=pk2(W17,W31);g_WBp[16]=pk2(W18,W32);g_WBp[17]=pk2(W19,W16);
    g_WBp[18]=pk2(0.f,W30);g_WBp[19]=pk2(W20,W34);g_WBp[20]=pk2(W33,0.f);
    // pi (softmax), packed in pair order
    float pi[24];
    float m = -1e30f;
    for (int s = 0; s < 24; ++s) m = fmaxf(m, ik[s]);
    float Z = 0.f;
    for (int s = 0; s < 24; ++s) Z += __expf(ik[s] - m);
    for (int s = 0; s < 24; ++s) pi[s] = __expf(ik[s] - m) / Z;
    for (int k = 0; k < 12; ++k)
      g_piP[k] = pk2(pi[c_perm[2*k]], pi[c_perm[2*k+1]]);
  }
}

// ---------------------------------------------------------------------------
// setupB: emission table in pair-permuted column order (parallel, 27 blocks)
// ---------------------------------------------------------------------------
__global__ void setupB_kernel(const float* __restrict__ ew) {
  int idx = blockIdx.x * 192 + threadIdx.x;   // 27*192 = 5184 = 216*24
  int col = idx % 24, ctx = idx / 24;
  int s = c_perm[col];
  int pp = ctx / 36, rm = ctx - pp * 36;
  int p = rm / 6, c = rm - p * 6;
  float val = 1.f / 6.f;
  if (s < 17 && pp < 4 && p < 4 && c < 4) {
    const float* e = ew + (((s * 4) + pp) * 4 + p) * 4;
    float m = fmaxf(fmaxf(e[0], e[1]), fmaxf(e[2], e[3]));
    float Z = __expf(e[0] - m) + __expf(e[1] - m) +
              __expf(e[2] - m) + __expf(e[3] - m);
    val = __expf(e[c] - m) / Z;
  }
  g_BtP[idx] = val;
}

// ---------------------------------------------------------------------------
#define ULO(x) ((unsigned)(x))
#define UHI(x) ((unsigned)((x) >> 32))
#define PKU(d, lo, hi) \
  asm("mov.b64 %0, {%1, %2};" : "=l"(d) : "r"(lo), "r"(hi))
#define FMA2(d, a, b, c) \
  asm("fma.rn.f32x2 %0, %1, %2, %3;" : "=l"(d) : "l"(a), "l"(b), "l"(c))
#define MUL2(d, a, b) \
  asm("mul.rn.f32x2 %0, %1, %2;" : "=l"(d) : "l"(a), "l"(b))
#define ADD2(d, a, b) \
  asm("add.rn.f32x2 %0, %1, %2;" : "=l"(d) : "l"(a), "l"(b))
#define FLOAT_OF(u) __uint_as_float(u)

// load 12 packed E pairs for a context (6x LDS.128)
#define ELOADP(CTX)                                                         \
  const ulonglong2* _ep = (const ulonglong2*)(sBt + (CTX) * 24);            \
  ulonglong2 _eA = _ep[0], _eB = _ep[1], _eC = _ep[2];                      \
  ulonglong2 _eD = _ep[3], _eE = _ep[4], _eF = _ep[5];

#define EAPPLYP()                                                           \
  MUL2(q0, t0, _eA.x);  MUL2(q1, t1, _eA.y);                                \
  MUL2(q2, t2, _eB.x);  MUL2(q3, t3, _eB.y);                                \
  MUL2(q4, t4, _eC.x);  MUL2(q5, t5, _eC.y);                                \
  MUL2(q6, t6, _eD.x);  MUL2(q7, t7, _eD.y);                                \
  MUL2(q8, t8, _eE.x);  MUL2(q9, t9, _eE.y);                                \
  MUL2(q10, t10, _eF.x); MUL2(q11, t11, _eF.y);

// forward packed step
#define FSTEP_P(CTX) {                                                      \
  ELOADP(CTX)                                                               \
  u64 Fa0, Fa12, Fa3, Fa6, Fa9, Fa16, Fa19, Fa22, Fc;                       \
  PKU(Fa0,  ULO(q0),  ULO(q0));                                             \
  PKU(Fa12, UHI(q0),  ULO(q1));                                             \
  PKU(Fa3,  UHI(q1),  UHI(q1));                                             \
  PKU(Fa6,  ULO(q4),  ULO(q4));                                             \
  PKU(Fa9,  ULO(q7),  ULO(q7));                                             \
  PKU(Fa16, UHI(q4),  UHI(q4));                                             \
  PKU(Fa19, UHI(q7),  UHI(q7));                                             \
  PKU(Fa22, UHI(q10), UHI(q10));                                            \
  PKU(Fc,   ULO(q10), ULO(q11));                                            \
  u64 t0,t1,t2,t3,t4,t5,t6,t7,t8,t9,t10,t11;                                \
  MUL2(t0, WP0, Fa0);                                                       \
  MUL2(t1, WP1, Fa12);                                                      \
  MUL2(t2, WP2, Fa3);  FMA2(t2, WP3, Fa16, t2);                             \
  MUL2(t3, WP4, q2);                                                        \
  MUL2(t4, WP5, q3);                                                        \
  MUL2(t5, WP6, Fa3);  FMA2(t5, WP7, Fa6, t5);  FMA2(t5, WP8, Fa19, t5);    \
  MUL2(t6, WP9, q5);                                                        \
  MUL2(t7, WP10, q6);                                                       \
  MUL2(t8, WP11, Fa3); FMA2(t8, WP12, Fa6, t8);                             \
  FMA2(t8, WP13, Fa9, t8); FMA2(t8, WP14, Fa22, t8);                        \
  MUL2(t9, WP15, q8);                                                       \
  MUL2(t10, WP16, q9);                                                      \
  MUL2(t11, WP17, Fc); FMA2(t11, WP18, q11, t11);                           \
  EAPPLYP() }

// backward packed matvec into t0..t11 (shared by BSTEP_P and final convert)
#define BMATP()                                                             \
  u64 G0,G1,G2,G3,G4,G5,G6,G7,G8,G9,G10,G11,G12,G13;                        \
  PKU(G0,  ULO(q0),  ULO(q1));                                              \
  PKU(G1,  UHI(q0),  UHI(q0));                                              \
  PKU(G2,  UHI(q1),  ULO(q2));                                              \
  PKU(G3,  ULO(q5),  ULO(q5));                                              \
  PKU(G4,  ULO(q8),  ULO(q8));                                              \
  PKU(G5,  UHI(q2),  UHI(q2));                                              \
  PKU(G6,  ULO(q5),  ULO(q2));                                              \
  PKU(G7,  ULO(q8),  UHI(q2));                                              \
  PKU(G8,  UHI(q5),  UHI(q5));                                              \
  PKU(G9,  ULO(q8),  ULO(q5));                                              \
  PKU(G10, UHI(q8),  UHI(q5));                                              \
  PKU(G11, ULO(q11), ULO(q8));                                              \
  PKU(G12, UHI(q8),  UHI(q8));                                              \
  PKU(G13, UHI(q11), UHI(q11));                                             \
  u64 t0,t1,t2,t3,t4,t5,t6,t7,t8,t9,t10,t11;                                \
  MUL2(t0, WP0, G0);  FMA2(t0, WP1, G1, t0);                                \
  MUL2(t1, WP2, G2);  FMA2(t1, WP3, G3, t1);                                \
  FMA2(t1, WP4, G4, t1); FMA2(t1, WP5, G5, t1);                             \
  MUL2(t2, WP6, q3);                                                        \
  MUL2(t3, WP7, q4);                                                        \
  MUL2(t4, WP8, G6);  FMA2(t4, WP9, G7, t4);  FMA2(t4, WP10, G8, t4);       \
  MUL2(t5, WP11, q6);                                                       \
  MUL2(t6, WP12, q7);                                                       \
  MUL2(t7, WP13, G9); FMA2(t7, WP14, G10, t7);                              \
  MUL2(t8, WP15, q9);                                                       \
  MUL2(t9, WP16, q10);                                                      \
  MUL2(t10, WP17, G11); FMA2(t10, WP18, G12, t10);                          \
  MUL2(t11, WP19, q11); FMA2(t11, WP20, G13, t11);

#define BSTEP_P(CTX) {                                                      \
  ELOADP(CTX)                                                               \
  BMATP()                                                                   \
  EAPPLYP() }

// exact power-of-two renorm on packed state
#define RENORMP() {                                                         \
  u64 _s0, _s1, _s2, _s3, _s4, _s5, _sa, _sb, _sc2, _st;                    \
  ADD2(_s0, q0, q1);  ADD2(_s1, q2, q3);  ADD2(_s2, q4, q5);                \
  ADD2(_s3, q6, q7);  ADD2(_s4, q8, q9);  ADD2(_s5, q10, q11);              \
  ADD2(_sa, _s0, _s1); ADD2(_sb, _s2, _s3); ADD2(_sc2, _s4, _s5);           \
  ADD2(_st, _sa, _sb); ADD2(_st, _st, _sc2);                                \
  float _z = FLOAT_OF(ULO(_st)) + FLOAT_OF(UHI(_st));                       \
  int _ez = ((__float_as_int(_z) >> 23) & 0xff) - 127;                      \
  float _sc = __int_as_float((127 - _ez) << 23);                            \
  K += _ez;                                                                 \
  u64 _SC; PKU(_SC, __float_as_uint(_sc), __float_as_uint(_sc));            \
  MUL2(q0, q0, _SC);  MUL2(q1, q1, _SC);  MUL2(q2, q2, _SC);                \
  MUL2(q3, q3, _SC);  MUL2(q4, q4, _SC);  MUL2(q5, q5, _SC);                \
  MUL2(q6, q6, _SC);  MUL2(q7, q7, _SC);  MUL2(q8, q8, _SC);                \
  MUL2(q9, q9, _SC);  MUL2(q10, q10, _SC); MUL2(q11, q11, _SC); }

// fwd group g (4 steps), chunks prv = g-1, cur = g; prefetches g+1
#define GROUPF(g) {                                                         \
  int4 _nxt = sp[(g) + 1];                                                  \
  FSTEP_P(prv.z*36 + prv.w*6 + cur.x);                                      \
  FSTEP_P(prv.w*36 + cur.x*6 + cur.y);                                      \
  FSTEP_P(cur.x*36 + cur.y*6 + cur.z);                                      \
  FSTEP_P(cur.y*36 + cur.z*6 + cur.w);                                      \
  prv = cur; cur = _nxt; }

// bwd group g (4 steps descending); chunk cur = g, reads prv = g-1
#define GROUPB(g) {                                                         \
  int4 _prv = sp[(g) - 1];                                                  \
  BSTEP_P(cur.y*36 + cur.z*6 + cur.w);                                      \
  BSTEP_P(cur.x*36 + cur.y*6 + cur.z);                                      \
  BSTEP_P(_prv.w*36 + cur.x*6 + cur.y);                                     \
  BSTEP_P(_prv.z*36 + _prv.w*6 + cur.x);                                    \
  cur = _prv; }

__global__ void __launch_bounds__(32)
scan_kernel(const int* __restrict__ seq, int T) {
  __shared__ __align__(16) float sBt[216 * 24];
  int lane = threadIdx.x;
  {
    const float4* srcp = (const float4*)g_BtP;
    float4* dstp = (float4*)sBt;
    for (int i = lane; i < 1296; i += 32) dstp[i] = srcp[i];
  }
  __syncwarp();

  int task = blockIdx.x * 32 + lane;
  int nb2 = (int)gridDim.x * 16;          // tasks per half = 2048
  int isF = task < nb2;
  int row = isF ? task : task - nb2;
  const int4* sp = (const int4*)(seq + (long long)row * T);

  u64 q0,q1,q2,q3,q4,q5,q6,q7,q8,q9,q10,q11;
  int K = 0;
  int HC = T / 8;                 // 250 groups per half
  int n5 = (HC - 1) / 5;          // 49
  int rem = (HC - 1) - n5 * 5;    // 4

  if (isF) {
    // packed fwd weights
    u64 WP0=g_WFp[0], WP1=g_WFp[1], WP2=g_WFp[2], WP3=g_WFp[3], WP4=g_WFp[4];
    u64 WP5=g_WFp[5], WP6=g_WFp[6], WP7=g_WFp[7], WP8=g_WFp[8], WP9=g_WFp[9];
    u64 WP10=g_WFp[10], WP11=g_WFp[11], WP12=g_WFp[12], WP13=g_WFp[13];
    u64 WP14=g_WFp[14], WP15=g_WFp[15], WP16=g_WFp[16], WP17=g_WFp[17];
    u64 WP18=g_WFp[18];

    int4 cur = sp[0];
    {
      // t=0: q = pi * E(ctx 4,4,s0)
      ELOADP(168 + cur.x)
      q0=g_piP[0]; q1=g_piP[1]; q2=g_piP[2]; q3=g_piP[3];
      q4=g_piP[4]; q5=g_piP[5]; q6=g_piP[6]; q7=g_piP[7];
      q8=g_piP[8]; q9=g_piP[9]; q10=g_piP[10]; q11=g_piP[11];
      MUL2(q0, q0, _eA.x);  MUL2(q1, q1, _eA.y);
      MUL2(q2, q2, _eB.x);  MUL2(q3, q3, _eB.y);
      MUL2(q4, q4, _eC.x);  MUL2(q5, q5, _eC.y);
      MUL2(q6, q6, _eD.x);  MUL2(q7, q7, _eD.y);
      MUL2(q8, q8, _eE.x);  MUL2(q9, q9, _eE.y);
      MUL2(q10, q10, _eF.x); MUL2(q11, q11, _eF.y);
    }
    FSTEP_P(144 + cur.x*6 + cur.y);
    FSTEP_P(cur.x*36 + cur.y*6 + cur.z);
    FSTEP_P(cur.y*36 + cur.z*6 + cur.w);
    int4 prv = cur;
    cur = sp[1];
    int g = 1;
    for (int it = 0; it < n5; ++it) {
      GROUPF(g); GROUPF(g + 1); GROUPF(g + 2); GROUPF(g + 3); GROUPF(g + 4);
      g += 5;
      RENORMP();
    }
    for (int r = 0; r < rem; ++r) { GROUPF(g); ++g; }
  } else {
    // packed bwd weights (reuse WP names so macros apply)
    u64 WP0=g_WBp[0], WP1=g_WBp[1], WP2=g_WBp[2], WP3=g_WBp[3], WP4=g_WBp[4];
    u64 WP5=g_WBp[5], WP6=g_WBp[6], WP7=g_WBp[7], WP8=g_WBp[8], WP9=g_WBp[9];
    u64 WP10=g_WBp[10], WP11=g_WBp[11], WP12=g_WBp[12], WP13=g_WBp[13];
    u64 WP14=g_WBp[14], WP15=g_WBp[15], WP16=g_WBp[16], WP17=g_WBp[17];
    u64 WP18=g_WBp[18], WP19=g_WBp[19], WP20=g_WBp[20];

    int CH = T / 4;                       // 500 chunks
    int4 cur = sp[CH - 1];
    int4 prv0 = sp[CH - 2];
    {
      // t = T-1: m = E(ctx)   (u_T = 1)
      ELOADP(cur.y*36 + cur.z*6 + cur.w)
      q0=_eA.x; q1=_eA.y; q2=_eB.x; q3=_eB.y; q4=_eC.x; q5=_eC.y;
      q6=_eD.x; q7=_eD.y; q8=_eE.x; q9=_eE.y; q10=_eF.x; q11=_eF.y;
    }
    BSTEP_P(cur.x*36 + cur.y*6 + cur.z);
    BSTEP_P(prv0.w*36 + cur.x*6 + cur.y);
    BSTEP_P(prv0.z*36 + prv0.w*6 + cur.x);
    cur = prv0;
    int g = CH - 2;
    for (int it = 0; it < n5; ++it) {
      GROUPB(g); GROUPB(g - 1); GROUPB(g - 2); GROUPB(g - 3); GROUPB(g - 4);
      g -= 5;
      RENORMP();
    }
    for (int r = 0; r < rem; ++r) { GROUPB(g); --g; }
    // final conversion: u = A m (no emission)
    {
      BMATP()
      q0=t0; q1=t1; q2=t2; q3=t3; q4=t4; q5=t5;
      q6=t6; q7=t7; q8=t8; q9=t9; q10=t10; q11=t11;
    }
  }

  u64* ov = g_vecP[task];
  ov[0]=q0; ov[1]=q1; ov[2]=q2; ov[3]=q3; ov[4]=q4; ov[5]=q5;
  ov[6]=q6; ov[7]=q7; ov[8]=q8; ov[9]=q9; ov[10]=q10; ov[11]=q11;
  g_Kv[task] = (float)K;
}

// ---------------------------------------------------------------------------
__global__ void combine_kernel(float* __restrict__ out, int batch) {
  int r = blockIdx.x * 256 + threadIdx.x;
  if (r >= batch) return;
  const u64* fa = g_vecP[r];
  const u64* fb = g_vecP[r + batch];
  float dot = 0.f;
#pragma unroll
  for (int k = 0; k < 12; ++k) {
    u64 a = fa[k], b = fb[k];
    dot = fmaf(FLOAT_OF(ULO(a)), FLOAT_OF(ULO(b)), dot);
    dot = fmaf(FLOAT_OF(UHI(a)), FLOAT_OF(UHI(b)), dot);
  }
  out[r] = (__log2f(dot) + g_Kv[r] + g_Kv[r + batch]) *
           0.69314718055994530942f;
}

// ---------------------------------------------------------------------------
extern "C" void kernel_launch(void* const* d_in, const int* in_sizes, int n_in,
                              void* d_out, int out_size) {
  const float* w  = (const float*)d_in[0];   // transition_kernel (240)
  const float* ew = (const float*)d_in[1];   // emission_kernel (1088)
  const float* ik = (const float*)d_in[2];   // init_kernel (24)
  const int* seq  = (const int*)d_in[3];     // (batch, T)
  float* out = (float*)d_out;

  int batch = out_size;                      // 2048
  int T = in_sizes[3] / batch;               // 2000

  setupA_kernel<<<1, 64>>>(w, ik);
  setupB_kernel<<<27, 192>>>(ew);
  scan_kernel<<<batch * 2 / 32, 32>>>(seq, T);
  combine_kernel<<<(batch + 255) / 256, 256>>>(out, batch);
}

// round 16
// speedup vs baseline: 2.1181x; 1.3079x over previous
#include <cuda_runtime.h>
#include <math.h>

// ---------------------------------------------------------------------------
// HMM forward (CgpHmmCell, nCodons=2), 24 states, T=2000, batch=2048.
// Transposed layout (R11): one lane owns the full 24-state vector (12 f32x2
// register pairs, R12 pairing); zero cross-lane exchange; fwd/bwd time split.
// R13: E-table row compressed 96B -> 56B (5 exact f32x2 pairs + 7 bf16 +
// exact 1/6 constant for non-emitting states), stride 80B for full bank
// spread; E double-buffered one step ahead; unit-weight mults removed;
// 64-thread CTAs (2 warps/SM) to overlap smem conflict stalls.
// ---------------------------------------------------------------------------

typedef unsigned long long u64;

__device__ u64 g_WFp[19];            // fwd packed weights
__device__ u64 g_WBp[21];            // bwd packed weights
__device__ u64 g_piP[12];            // packed softmax(init), pair order
__device__ __align__(16) unsigned char g_BtE[216 * 80];  // compressed E rows
__device__ u64 g_vecP[4096][12];     // half-results (packed)
__device__ float g_Kv[4096];         // accumulated exponents

__constant__ int c_rcnt[24] = {2,1,1,4,1,1,3,1,1,2,1,1,1,2,1,1,2,1,1,2,1,1,2,1};
__constant__ int c_rcols[24][4] = {
  {0,1,0,0},{2,0,0,0},{3,0,0,0},{4,14,7,10},{5,0,0,0},{6,0,0,0},{7,17,10,0},
  {8,0,0,0},{9,0,0,0},{20,10,0,0},{11,0,0,0},{12,0,0,0},{13,0,0,0},{13,23,0,0},
  {15,0,0,0},{16,0,0,0},{4,14,0,0},{18,0,0,0},{19,0,0,0},{7,17,0,0},{21,0,0,0},
  {22,0,0,0},{10,20,0,0},{23,0,0,0}};
__constant__ int c_perm[24] = {0,1, 2,3, 4,14, 5,15, 6,16, 7,17, 8,18, 9,19,
                               10,20, 11,21, 12,22, 13,23};

__device__ __forceinline__ u64 pk2(float lo, float hi) {
  return ((u64)__float_as_uint(hi) << 32) | (u64)__float_as_uint(lo);
}
__device__ __forceinline__ unsigned bf16of(float v) {   // RN-even bf16 bits
  unsigned b = __float_as_uint(v);
  unsigned lsb = (b >> 16) & 1u;
  return (b + 0x7FFFu + lsb) >> 16;
}

// ---------------------------------------------------------------------------
__global__ void setupA_kernel(const float* __restrict__ w,
                              const float* __restrict__ ik) {
  __shared__ float V[24][24];
  __shared__ float A[24][24];
  int tid = threadIdx.x;
  for (int i = tid; i < 576; i += blockDim.x) {
    ((float*)V)[i] = 0.f;
    ((float*)A)[i] = 0.f;
  }
  __syncthreads();
  if (tid == 0) {
    float w12 = w[12];
    V[0][0]  = 1.f - w[0]; V[0][1]  = w[0];
    V[1][2]  = 1.f;        V[2][3]  = 1.f;
    V[3][4]  = w[1];       V[6][7]  = w[2];
    V[4][5]  = 1.f; V[7][8] = 1.f; V[5][6] = 1.f; V[8][9] = 1.f;
    V[3][14] = w[3]; V[6][17] = w[4]; V[9][20] = w[5];
    V[9][10] = 1.f - w[5];
    V[14][15] = 1.f; V[17][18] = 1.f; V[20][21] = 1.f;
    V[15][16] = 1.f; V[18][19] = 1.f; V[21][22] = 1.f;
    V[16][4] = w[6]; V[19][7] = w[7]; V[22][10] = w[8];
    V[16][14] = 1.f - w[9]; V[19][17] = 1.f - w[10]; V[22][20] = 1.f - w[11];
    V[3][7]  = 1.f - w12 * w12;
    V[3][10] = 1.f - w12 * w12 * w12;
    V[6][10] = 1.f - w12 * w12;
    V[10][11] = 1.f; V[11][12] = 1.f; V[12][13] = 1.f;
    V[13][13] = 1.f; V[13][23] = 1.f; V[23][23] = 1.f;
  }
  __syncthreads();
  if (tid < 24) {
    int n = c_rcnt[tid];
    float m = -1e30f;
    for (int i = 0; i < n; ++i) m = fmaxf(m, V[tid][c_rcols[tid][i]]);
    float Z = 0.f;
    for (int i = 0; i < n; ++i) Z += __expf(V[tid][c_rcols[tid][i]] - m);
    for (int i = 0; i < n; ++i) {
      int c = c_rcols[tid][i];
      A[tid][c] = __expf(V[tid][c] - m) / Z;
    }
  }
  __syncthreads();
  if (tid == 0) {
    float W0=A[0][0],  W1=A[0][1],  W2=A[1][2],  W3=A[2][3],  W4=A[3][4];
    float W5=A[16][4], W6=A[4][5],  W7=A[5][6],  W8=A[3][7],  W9=A[6][7];
    float W10=A[19][7],W11=A[7][8], W12=A[8][9], W13=A[3][10],W14=A[6][10];
    float W15=A[9][10],W16=A[22][10],W17=A[10][11],W18=A[11][12],W19=A[12][13];
    float W20=A[13][13],W21=A[3][14],W22=A[16][14],W23=A[14][15],W24=A[15][16];
    float W25=A[6][17],W26=A[19][17],W27=A[17][18],W28=A[18][19],W29=A[9][20];
    float W30=A[22][20],W31=A[20][21],W32=A[21][22],W33=A[13][23],W34=A[23][23];
    g_WFp[0]=pk2(W0,W1);   g_WFp[1]=pk2(W2,W3);   g_WFp[2]=pk2(W4,W21);
    g_WFp[3]=pk2(W5,W22);  g_WFp[4]=pk2(W6,W23);  g_WFp[5]=pk2(W7,W24);
    g_WFp[6]=pk2(W8,0.f);  g_WFp[7]=pk2(W9,W25);  g_WFp[8]=pk2(W10,W26);
    g_WFp[9]=pk2(W11,W27); g_WFp[10]=pk2(W12,W28);g_WFp[11]=pk2(W13,0.f);
    g_WFp[12]=pk2(W14,0.f);g_WFp[13]=pk2(W15,W29);g_WFp[14]=pk2(W16,W30);
    g_WFp[15]=pk2(W17,W31);g_WFp[16]=pk2(W18,W32);g_WFp[17]=pk2(W19,W33);
    g_WFp[18]=pk2(W20,W34);
    g_WBp[0]=pk2(W0,W2);   g_WBp[1]=pk2(W1,0.f);  g_WBp[2]=pk2(W3,W4);
    g_WBp[3]=pk2(0.f,W8);  g_WBp[4]=pk2(0.f,W13); g_WBp[5]=pk2(0.f,W21);
    g_WBp[6]=pk2(W6,W23);  g_WBp[7]=pk2(W7,W24);  g_WBp[8]=pk2(W9,W5);
    g_WBp[9]=pk2(W14,W22); g_WBp[10]=pk2(W25,0.f);g_WBp[11]=pk2(W11,W27);
    g_WBp[12]=pk2(W12,W28);g_WBp[13]=pk2(W15,W10);g_WBp[14]=pk2(W29,W26);
    g_WBp[15]=pk2(W17,W31);g_WBp[16]=pk2(W18,W32);g_WBp[17]=pk2(W19,W16);
    g_WBp[18]=pk2(0.f,W30);g_WBp[19]=pk2(W20,W34);g_WBp[20]=pk2(W33,0.f);
    float pi[24];
    float m = -1e30f;
    for (int s = 0; s < 24; ++s) m = fmaxf(m, ik[s]);
    float Z = 0.f;
    for (int s = 0; s < 24; ++s) Z += __expf(ik[s] - m);
    for (int s = 0; s < 24; ++s) pi[s] = __expf(ik[s] - m) / Z;
    for (int k = 0; k < 12; ++k)
      g_piP[k] = pk2(pi[c_perm[2*k]], pi[c_perm[2*k+1]]);
  }
}

// ---------------------------------------------------------------------------
// setupB: compressed E rows.  Row (80B stride, 56B payload):
//  u64[0..4]: f32x2 pairs (0,1)(2,3)(4,14)(5,15)(6,16)
//  u64[5]: bf16 quad {B7,B8,B9,B10}   u64[6]: {B11,B12,B13,pad}
// ---------------------------------------------------------------------------
__global__ void setupB_kernel(const float* __restrict__ ew) {
  __shared__ float v[24];
  int ctx = blockIdx.x;      // 216
  int s = threadIdx.x;       // 32
  if (s < 24) {
    int pp = ctx / 36, rm = ctx - pp * 36;
    int p = rm / 6, c = rm - p * 6;
    float val = 1.f / 6.f;
    if (s < 17 && pp < 4 && p < 4 && c < 4) {
      const float* e = ew + (((s * 4) + pp) * 4 + p) * 4;
      float m = fmaxf(fmaxf(e[0], e[1]), fmaxf(e[2], e[3]));
      float Z = __expf(e[0] - m) + __expf(e[1] - m) +
                __expf(e[2] - m) + __expf(e[3] - m);
      val = __expf(e[c] - m) / Z;
    }
    v[s] = val;
  }
  __syncwarp();
  if (s == 0) {
    u64* row = (u64*)(g_BtE + ctx * 80);
    row[0] = pk2(v[0], v[1]);
    row[1] = pk2(v[2], v[3]);
    row[2] = pk2(v[4], v[14]);
    row[3] = pk2(v[5], v[15]);
    row[4] = pk2(v[6], v[16]);
    unsigned qa_lo = bf16of(v[7])  | (bf16of(v[8])  << 16);
    unsigned qa_hi = bf16of(v[9])  | (bf16of(v[10]) << 16);
    unsigned qb_lo = bf16of(v[11]) | (bf16of(v[12]) << 16);
    unsigned qb_hi = bf16of(v[13]);
    row[5] = ((u64)qa_hi << 32) | qa_lo;
    row[6] = ((u64)qb_hi << 32) | qb_lo;
  }
}

// ---------------------------------------------------------------------------
#define ULO(x) ((unsigned)(x))
#define UHI(x) ((unsigned)((x) >> 32))
#define PKU(d, lo, hi) \
  asm("mov.b64 %0, {%1, %2};" : "=l"(d) : "r"(lo), "r"(hi))
#define FMA2(d, a, b, c) \
  asm("fma.rn.f32x2 %0, %1, %2, %3;" : "=l"(d) : "l"(a), "l"(b), "l"(c))
#define MUL2(d, a, b) \
  asm("mul.rn.f32x2 %0, %1, %2;" : "=l"(d) : "l"(a), "l"(b))
#define ADD2(d, a, b) \
  asm("add.rn.f32x2 %0, %1, %2;" : "=l"(d) : "l"(a), "l"(b))
#define FLOAT_OF(u) __uint_as_float(u)

// load compressed E row into 7 u64 buffer regs (3x LDS.128 + 1x LDS.64)
#define ELOAD_TO(U, CTX) {                                                  \
  const unsigned char* _pb = sBt + (CTX) * 80;                              \
  ulonglong2 _y0 = *(const ulonglong2*)_pb;                                 \
  ulonglong2 _y1 = *(const ulonglong2*)(_pb + 16);                          \
  ulonglong2 _y2 = *(const ulonglong2*)(_pb + 32);                          \
  u64 _y3 = *(const u64*)(_pb + 48);                                        \
  U##0 = _y0.x; U##1 = _y0.y; U##2 = _y1.x; U##3 = _y1.y;                   \
  U##4 = _y2.x; U##5 = _y2.y; U##6 = _y3; }

// unpack bf16 tail (shift-by-16 = exact bf16->f32), build pairs with exact
// 1/6 const, multiply sources by E, commit to q
#define EAPPLY_CORE(U, S0,S1,S2,S3,S4,S5,S6,S7,S8,S9,S10,S11) {             \
  unsigned _wA = ULO(U##5), _wB = UHI(U##5);                                \
  unsigned _wC = ULO(U##6), _wD = UHI(U##6);                                \
  u64 _E5,_E6,_E7,_E8,_E9,_E10,_E11;                                        \
  PKU(_E5,  _wA << 16,          SIXF);                                      \
  PKU(_E6,  _wA & 0xFFFF0000u,  SIXF);                                      \
  PKU(_E7,  _wB << 16,          SIXF);                                      \
  PKU(_E8,  _wB & 0xFFFF0000u,  SIXF);                                      \
  PKU(_E9,  _wC << 16,          SIXF);                                      \
  PKU(_E10, _wC & 0xFFFF0000u,  SIXF);                                      \
  PKU(_E11, _wD << 16,          SIXF);                                      \
  u64 _r0,_r1,_r2,_r3,_r4,_r5,_r6,_r7,_r8,_r9,_r10,_r11;                    \
  MUL2(_r0, S0, U##0);  MUL2(_r1, S1, U##1);  MUL2(_r2, S2, U##2);          \
  MUL2(_r3, S3, U##3);  MUL2(_r4, S4, U##4);  MUL2(_r5, S5, _E5);           \
  MUL2(_r6, S6, _E6);   MUL2(_r7, S7, _E7);   MUL2(_r8, S8, _E8);           \
  MUL2(_r9, S9, _E9);   MUL2(_r10, S10, _E10); MUL2(_r11, S11, _E11);       \
  q0=_r0; q1=_r1; q2=_r2; q3=_r3; q4=_r4; q5=_r5;                           \
  q6=_r6; q7=_r7; q8=_r8; q9=_r9; q10=_r10; q11=_r11; }

// fwd step: uses E in UIN, prefetches CTXN into ULD.  Unit-weight targets
// pass alpha pairs straight through to the E multiply.
#define FSTEP_P(UIN, ULD, CTXN) {                                           \
  ELOAD_TO(ULD, CTXN)                                                       \
  u64 Fa0, Fa12, Fa3, Fa6, Fa9, Fa16, Fa19, Fa22, Fc;                       \
  PKU(Fa0,  ULO(q0),  ULO(q0));                                             \
  PKU(Fa12, UHI(q0),  ULO(q1));                                             \
  PKU(Fa3,  UHI(q1),  UHI(q1));                                             \
  PKU(Fa6,  ULO(q4),  ULO(q4));                                             \
  PKU(Fa9,  ULO(q7),  ULO(q7));                                             \
  PKU(Fa16, UHI(q4),  UHI(q4));                                             \
  PKU(Fa19, UHI(q7),  UHI(q7));                                             \
  PKU(Fa22, UHI(q10), UHI(q10));                                            \
  PKU(Fc,   ULO(q10), ULO(q11));                                            \
  u64 t0, t2, t5, t8, t11;                                                  \
  MUL2(t0, WF0, Fa0);                                                       \
  MUL2(t2, WF2, Fa3);  FMA2(t2, WF3, Fa16, t2);                             \
  MUL2(t5, WF6, Fa3);  FMA2(t5, WF7, Fa6, t5);  FMA2(t5, WF8, Fa19, t5);    \
  MUL2(t8, WF11, Fa3); FMA2(t8, WF12, Fa6, t8);                             \
  FMA2(t8, WF13, Fa9, t8); FMA2(t8, WF14, Fa22, t8);                        \
  MUL2(t11, WF17, Fc); FMA2(t11, WF18, q11, t11);                           \
  EAPPLY_CORE(UIN, t0, Fa12, t2, q2, q3, t5, q5, q6, t8, q8, q9, t11)       \
}

// bwd matvec core (weighted targets only; unit targets pass through)
#define BMAT_CORE()                                                         \
  u64 G0,G1,G2,G3,G4,G5,G6,G7,G8,G9,G10,G11,G12,G13;                        \
  PKU(G0,  ULO(q0),  ULO(q1));                                              \
  PKU(G1,  UHI(q0),  UHI(q0));                                              \
  PKU(G2,  UHI(q1),  ULO(q2));                                              \
  PKU(G3,  ULO(q5),  ULO(q5));                                              \
  PKU(G4,  ULO(q8),  ULO(q8));                                              \
  PKU(G5,  UHI(q2),  UHI(q2));                                              \
  PKU(G6,  ULO(q5),  ULO(q2));                                              \
  PKU(G7,  ULO(q8),  UHI(q2));                                              \
  PKU(G8,  UHI(q5),  UHI(q5));                                              \
  PKU(G9,  ULO(q8),  ULO(q5));                                              \
  PKU(G10, UHI(q8),  UHI(q5));                                              \
  PKU(G11, ULO(q11), ULO(q8));                                              \
  PKU(G12, UHI(q8),  UHI(q8));                                              \
  PKU(G13, UHI(q11), UHI(q11));                                             \
  u64 t0, t1, t4, t7, t10, t11;                                             \
  MUL2(t0, WB0, G0);  FMA2(t0, WB1, G1, t0);                                \
  MUL2(t1, WB2, G2);  FMA2(t1, WB3, G3, t1);                                \
  FMA2(t1, WB4, G4, t1); FMA2(t1, WB5, G5, t1);                             \
  MUL2(t4, WB8, G6);  FMA2(t4, WB9, G7, t4);  FMA2(t4, WB10, G8, t4);       \
  MUL2(t7, WB13, G9); FMA2(t7, WB14, G10, t7);                              \
  MUL2(t10, WB17, G11); FMA2(t10, WB18, G12, t10);                          \
  MUL2(t11, WB19, q11); FMA2(t11, WB20, G13, t11);

#define BSTEP_P(UIN, ULD, CTXN) {                                           \
  ELOAD_TO(ULD, CTXN)                                                       \
  BMAT_CORE()                                                               \
  EAPPLY_CORE(UIN, t0, t1, q3, q4, t4, q6, q7, t7, q9, q10, t10, t11)       \
}

#define RENORMP() {                                                         \
  u64 _s0, _s1, _s2, _s3, _s4, _s5, _sa, _sb, _sc2, _st;                    \
  ADD2(_s0, q0, q1);  ADD2(_s1, q2, q3);  ADD2(_s2, q4, q5);                \
  ADD2(_s3, q6, q7);  ADD2(_s4, q8, q9);  ADD2(_s5, q10, q11);              \
  ADD2(_sa, _s0, _s1); ADD2(_sb, _s2, _s3); ADD2(_sc2, _s4, _s5);           \
  ADD2(_st, _sa, _sb); ADD2(_st, _st, _sc2);                                \
  float _z = FLOAT_OF(ULO(_st)) + FLOAT_OF(UHI(_st));                       \
  int _ez = ((__float_as_int(_z) >> 23) & 0xff) - 127;                      \
  float _sc = __int_as_float((127 - _ez) << 23);                            \
  K += _ez;                                                                 \
  u64 _SC; PKU(_SC, __float_as_uint(_sc), __float_as_uint(_sc));            \
  MUL2(q0, q0, _SC);  MUL2(q1, q1, _SC);  MUL2(q2, q2, _SC);                \
  MUL2(q3, q3, _SC);  MUL2(q4, q4, _SC);  MUL2(q5, q5, _SC);                \
  MUL2(q6, q6, _SC);  MUL2(q7, q7, _SC);  MUL2(q8, q8, _SC);                \
  MUL2(q9, q9, _SC);  MUL2(q10, q10, _SC); MUL2(q11, q11, _SC); }

#define GROUPF(g) {                                                         \
  int4 _nxt = sp[(g) + 1];                                                  \
  int _c1 = prv.w*36 + cur.x*6 + cur.y;                                     \
  int _c2 = cur.x*36 + cur.y*6 + cur.z;                                     \
  int _c3 = cur.y*36 + cur.z*6 + cur.w;                                     \
  int _c4 = cur.z*36 + cur.w*6 + _nxt.x;                                    \
  FSTEP_P(UB, UA, _c1)                                                      \
  FSTEP_P(UA, UB, _c2)                                                      \
  FSTEP_P(UB, UA, _c3)                                                      \
  FSTEP_P(UA, UB, _c4)                                                      \
  prv = cur; cur = _nxt; }

#define GROUPB(g) {                                                         \
  int4 _prv = sp[(g) - 1];                                                  \
  int _c2 = cur.x*36 + cur.y*6 + cur.z;                                     \
  int _c1 = _prv.w*36 + cur.x*6 + cur.y;                                    \
  int _c0 = _prv.z*36 + _prv.w*6 + cur.x;                                   \
  int _cn = _prv.y*36 + _prv.z*6 + _prv.w;                                  \
  BSTEP_P(UB, UA, _c2)                                                      \
  BSTEP_P(UA, UB, _c1)                                                      \
  BSTEP_P(UB, UA, _c0)                                                      \
  BSTEP_P(UA, UB, _cn)                                                      \
  cur = _prv; }

__global__ void __launch_bounds__(64)
scan_kernel(const int* __restrict__ seq, int T) {
  static __shared__ __align__(16) unsigned char sBt[216 * 80];
  int tid = threadIdx.x;
  {
    const float4* srcp = (const float4*)g_BtE;
    float4* dstp = (float4*)sBt;
    for (int i = tid; i < 216 * 5; i += 64) dstp[i] = srcp[i];
  }
  __syncthreads();

  const unsigned SIXF = 0x3E2AAAABu;     // exact f32 bits of 1/6 (RN)

  int task = blockIdx.x * 64 + tid;      // 0..4095
  int nb2 = (int)gridDim.x * 32;         // 2048 tasks per half
  int isF = task < nb2;
  int row = isF ? task : task - nb2;
  const int4* sp = (const int4*)(seq + (long long)row * T);

  u64 q0,q1,q2,q3,q4,q5,q6,q7,q8,q9,q10,q11;
  u64 UA0,UA1,UA2,UA3,UA4,UA5,UA6;
  u64 UB0,UB1,UB2,UB3,UB4,UB5,UB6;
  int K = 0;
  int HC = T / 8;                 // 250 groups per half
  int n5 = (HC - 1) / 5;          // 49
  int rem = (HC - 1) - n5 * 5;    // 4

  if (isF) {
    u64 WF0=g_WFp[0], WF2=g_WFp[2], WF3=g_WFp[3], WF6=g_WFp[6];
    u64 WF7=g_WFp[7], WF8=g_WFp[8], WF11=g_WFp[11], WF12=g_WFp[12];
    u64 WF13=g_WFp[13], WF14=g_WFp[14], WF17=g_WFp[17], WF18=g_WFp[18];

    int4 cur = sp[0];
    int c0 = 168 + cur.x;                       // ctx (4,4,s0)
    ELOAD_TO(UB, c0)
    int c1 = 144 + cur.x*6 + cur.y;             // ctx (4,s0,s1)
    ELOAD_TO(UA, c1)
    {
      u64 p0=g_piP[0], p1=g_piP[1], p2=g_piP[2], p3=g_piP[3];
      u64 p4=g_piP[4], p5=g_piP[5], p6=g_piP[6], p7=g_piP[7];
      u64 p8=g_piP[8], p9=g_piP[9], p10=g_piP[10], p11=g_piP[11];
      EAPPLY_CORE(UB, p0,p1,p2,p3,p4,p5,p6,p7,p8,p9,p10,p11)   // t=0
    }
    int4 nxt0 = sp[1];
    int c2 = cur.x*36 + cur.y*6 + cur.z;
    int c3 = cur.y*36 + cur.z*6 + cur.w;
    int c4 = cur.z*36 + cur.w*6 + nxt0.x;
    FSTEP_P(UA, UB, c2)    // t=1
    FSTEP_P(UB, UA, c3)    // t=2
    FSTEP_P(UA, UB, c4)    // t=3
    int4 prv = cur;
    cur = nxt0;
    int g = 1;
    for (int it = 0; it < n5; ++it) {
      GROUPF(g); GROUPF(g + 1); GROUPF(g + 2); GROUPF(g + 3); GROUPF(g + 4);
      g += 5;
      RENORMP();
    }
    for (int r = 0; r < rem; ++r) { GROUPF(g); ++g; }
  } else {
    u64 WB0=g_WBp[0], WB1=g_WBp[1], WB2=g_WBp[2], WB3=g_WBp[3];
    u64 WB4=g_WBp[4], WB5=g_WBp[5], WB8=g_WBp[8], WB9=g_WBp[9];
    u64 WB10=g_WBp[10], WB13=g_WBp[13], WB14=g_WBp[14];
    u64 WB17=g_WBp[17], WB18=g_WBp[18], WB19=g_WBp[19], WB20=g_WBp[20];

    int CH = T / 4;                       // 500 chunks
    int4 cur = sp[CH - 1];
    int4 prv0 = sp[CH - 2];
    int c1999 = cur.y*36 + cur.z*6 + cur.w;
    ELOAD_TO(UB, c1999)
    int c1998 = cur.x*36 + cur.y*6 + cur.z;
    ELOAD_TO(UA, c1998)
    {
      u64 ONEP; PKU(ONEP, 0x3F800000u, 0x3F800000u);
      EAPPLY_CORE(UB, ONEP,ONEP,ONEP,ONEP,ONEP,ONEP,ONEP,ONEP,ONEP,ONEP,
                  ONEP,ONEP)                           // t=1999: m = E
    }
    int c1997 = prv0.w*36 + cur.x*6 + cur.y;
    int c1996 = prv0.z*36 + prv0.w*6 + cur.x;
    int c1995 = prv0.y*36 + prv0.z*6 + prv0.w;
    BSTEP_P(UA, UB, c1997)   // t=1998
    BSTEP_P(UB, UA, c1996)   // t=1997
    BSTEP_P(UA, UB, c1995)   // t=1996
    cur = prv0;
    int g = CH - 2;                       // 498
    for (int it = 0; it < n5; ++it) {
      GROUPB(g); GROUPB(g - 1); GROUPB(g - 2); GROUPB(g - 3); GROUPB(g - 4);
      g -= 5;
      RENORMP();
    }
    for (int r = 0; r < rem; ++r) { GROUPB(g); --g; }
    {
      // final conversion: u = A m (no emission)
      BMAT_CORE()
      u64 _n2=q3, _n3=q4, _n5=q6, _n6=q7, _n8=q9, _n9=q10;
      q0=t0; q1=t1; q2=_n2; q3=_n3; q4=t4; q5=_n5;
      q6=_n6; q7=t7; q8=_n8; q9=_n9; q10=t10; q11=t11;
    }
  }

  u64* ov = g_vecP[task];
  ov[0]=q0; ov[1]=q1; ov[2]=q2; ov[3]=q3; ov[4]=q4; ov[5]=q5;
  ov[6]=q6; ov[7]=q7; ov[8]=q8; ov[9]=q9; ov[10]=q10; ov[11]=q11;
  g_Kv[task] = (float)K;
}

// ---------------------------------------------------------------------------
__global__ void combine_kernel(float* __restrict__ out, int batch) {
  int r = blockIdx.x * 128 + threadIdx.x;
  if (r >= batch) return;
  const u64* fa = g_vecP[r];
  const u64* fb = g_vecP[r + batch];
  float dot = 0.f;
#pragma unroll
  for (int k = 0; k < 12; ++k) {
    u64 a = fa[k], b = fb[k];
    dot = fmaf(FLOAT_OF(ULO(a)), FLOAT_OF(ULO(b)), dot);
    dot = fmaf(FLOAT_OF(UHI(a)), FLOAT_OF(UHI(b)), dot);
  }
  out[r] = (__log2f(dot) + g_Kv[r] + g_Kv[r + batch]) *
           0.69314718055994530942f;
}

// ---------------------------------------------------------------------------
extern "C" void kernel_launch(void* const* d_in, const int* in_sizes, int n_in,
                              void* d_out, int out_size) {
  const float* w  = (const float*)d_in[0];   // transition_kernel (240)
  const float* ew = (const float*)d_in[1];   // emission_kernel (1088)
  const float* ik = (const float*)d_in[2];   // init_kernel (24)
  const int* seq  = (const int*)d_in[3];     // (batch, T)
  float* out = (float*)d_out;

  int batch = out_size;                      // 2048
  int T = in_sizes[3] / batch;               // 2000

  setupA_kernel<<<1, 64>>>(w, ik);
  setupB_kernel<<<216, 32>>>(ew);
  scan_kernel<<<batch * 2 / 64, 64>>>(seq, T);
  combine_kernel<<<(batch + 127) / 128, 128>>>(out, batch);
}